// round 14
// baseline (speedup 1.0000x reference)
#include <cuda_runtime.h>
#include <cstdint>
#include <cstddef>

// Problem constants
#define S_LEN 4096
#define D 2048
#define DV 512            // D / 4 (float4 columns)
#define NT 32000
#define NTV 8000          // NT / 4
#define INP 4097          // D + D + 1
#define N_NODES 4097      // S_LEN + 1
#define NP 256            // partial chunks for colsum / lmv stages
#define NBLK 296          // 2 blocks/SM on 148 SMs (co-resident by launch_bounds)
#define NTHR (NBLK * 256)
#define NWARP (NTHR / 32)

// ---------------- scratch (device globals; no allocation) ----------------
__device__ float g_bufA[NP * D];        // partial ping (2 MB)
__device__ float g_bufB[NP * D];        // partial pong (2 MB)
__device__ float g_vecA[D];             // reduced vector ping
__device__ float g_vecB[D];             // reduced vector pong
__device__ float g_inp[INP];            // LSTM input vector
__device__ float g_gsum[4 * D];         // gate pre-activations
__device__ float g_pout[16 * NT];       // output matvec partials (2 MB)
__device__ unsigned g_hbits[D / 32];    // per-warp ballots of cur_h != 0
__device__ unsigned g_hflag;            // OR of g_hbits (rewritten every launch)
__device__ unsigned g_bar_cnt;          // zero-init; always returns to 0
__device__ volatile unsigned g_bar_gen; // monotonically increasing generation

// ---------------- grid-wide barrier (all NBLK blocks co-resident) --------
__device__ __forceinline__ void grid_bar() {
    __syncthreads();
    if (threadIdx.x == 0) {
        unsigned gen = g_bar_gen;
        __threadfence();                       // publish this block's phase writes
        if (atomicAdd(&g_bar_cnt, 1u) == NBLK - 1u) {
            g_bar_cnt = 0u;
            __threadfence();                   // reset visible before release
            g_bar_gen = gen + 1u;
        } else {
            while (g_bar_gen == gen) { }
        }
    }
    __syncthreads();
}

__device__ __forceinline__ float sigf(float x) { return 1.f / (1.f + expf(-x)); }

// Vector reduce: one warp per column, single parallel round (2048 <= NWARP).
// Reduces NP partials for column c, applies epilogue, writes vout[c].
__device__ __forceinline__ void vec_reduce(const float* __restrict__ partin,
                                           float* __restrict__ vout,
                                           const float* __restrict__ addvec,
                                           float scale, int do_relu,
                                           int wg, int lane) {
    for (int c = wg; c < D; c += NWARP) {
        float a = 0.f;
        #pragma unroll
        for (int i = 0; i < 8; ++i)
            a += partin[(lane + i * 32) * D + c];
        #pragma unroll
        for (int o = 16; o; o >>= 1) a += __shfl_down_sync(0xffffffffu, a, o);
        if (lane == 0) {
            if (addvec) a += addvec[c];
            a *= scale;
            if (do_relu) a = fmaxf(a, 0.f);
            vout[c] = a;
        }
    }
}

// Pure-streaming matvec partials: no shared memory, no block syncs.
// item = chunk(8 rows) * DV + float4-col; iterations fully independent so
// W loads pipeline across items.
__device__ __forceinline__ void lmv_stream(const float* __restrict__ v,
                                           const float4* __restrict__ W4,
                                           float* __restrict__ partout, int g) {
    for (int item = g; item < NP * DV; item += NTHR) {
        int ky = item >> 9;                    // chunk of 8 k-rows
        int c4 = item & 511;
        int k0 = ky * 8;
        float4 a = make_float4(0.f, 0.f, 0.f, 0.f);
        #pragma unroll
        for (int j = 0; j < 8; ++j) {
            float s = __ldg(v + k0 + j);       // warp-uniform broadcast
            float4 w = W4[(size_t)(k0 + j) * DV + c4];
            a.x += s * w.x; a.y += s * w.y; a.z += s * w.z; a.w += s * w.w;
        }
        ((float4*)partout)[item] = a;          // item == ky*DV + c4
    }
}

// ---------------- the whole network in one persistent kernel -------------
__global__ void __launch_bounds__(256, 2) k_mega(
        const float* __restrict__ sen, const int* __restrict__ pos_raw,
        const float4* __restrict__ hid4,
        const float4* __restrict__ dim_up4, const float4* __restrict__ W_gcn4,
        const float4* __restrict__ dim_down4, const float4* __restrict__ dim_out4,
        const float* __restrict__ Wi, const float4* __restrict__ Wh4,
        const float* __restrict__ bi, const float* __restrict__ bh,
        const float* __restrict__ cur_h, const float* __restrict__ cur_cell,
        float* __restrict__ out) {
    __shared__ float vsh[128];
    int t = threadIdx.x;
    int g = blockIdx.x * 256 + t;
    int wg = g >> 5, lane = t & 31;

    // ---- P0: prep g_inp, ballot cur_h nonzeros, colsum partials -> bufA ----
    if (g < D) {
        g_inp[g] = sen[g];                     // sen_emb half of LSTM input
        unsigned b = __ballot_sync(0xffffffffu, cur_h[g] != 0.f);
        if (lane == 0) g_hbits[wg] = b;        // always overwritten: deterministic
    }
    if (g == D) {
        int bits = pos_raw[0];
        g_inp[2 * D] = (bits >= 0 && bits < 1000000) ? (float)bits
                                                     : __int_as_float(bits);
    }
    for (int item = g; item < NP * DV; item += NTHR) {
        int chunk = item >> 9, c4 = item & 511;
        float4 w[16];
        #pragma unroll
        for (int r = 0; r < 16; ++r)
            w[r] = hid4[(size_t)(chunk * 16 + r) * DV + c4];
        float4 a = make_float4(0.f, 0.f, 0.f, 0.f);
        #pragma unroll
        for (int r = 0; r < 16; ++r) {
            a.x += w[r].x; a.y += w[r].y; a.z += w[r].z; a.w += w[r].w;
        }
        ((float4*)g_bufA)[item] = a;           // item == chunk*DV + c4
    }
    grid_bar();

    // ---- graph chain: reduce / stream alternation ----
    vec_reduce(g_bufA, g_vecA, nullptr, 1.0f, 0, wg, lane);         // s = colsum
    grid_bar();
    lmv_stream(g_vecA, dim_up4, g_bufB, g);                         // s @ dim_up
    grid_bar();
    vec_reduce(g_bufB, g_vecB, cur_h, 1.0f / (float)N_NODES, 0, wg, lane);  // mean msg
    grid_bar();
    lmv_stream(g_vecB, W_gcn4, g_bufA, g);                          // m @ W_gcn
    grid_bar();
    vec_reduce(g_bufA, g_vecA, nullptr, 1.0f, 1, wg, lane);         // relu
    grid_bar();
    lmv_stream(g_vecA, dim_down4, g_bufB, g);                       // v2 @ dim_down
    grid_bar();

    // ---- P4: final reduce -> g_inp[D : 2D); flag OR ----
    if (g == 0) {
        unsigned f = 0;
        #pragma unroll
        for (int i = 0; i < D / 32; ++i) f |= g_hbits[i];
        g_hflag = f;                           // always overwritten: deterministic
    }
    vec_reduce(g_bufB, g_inp + D, nullptr, 1.0f, 0, wg, lane);      // graph_emb
    grid_bar();

    // ---- P5: LSTM gate pre-activations, warp per (gate,row) ----
    // Wh stream skipped when cur_h is identically zero (runtime-guarded).
    {
        unsigned hnz = g_hflag;
        for (int row = wg; row < 4 * D; row += NWARP) {
            const float* wi_row = Wi + (size_t)row * INP;
            float acc = 0.f;
            #pragma unroll
            for (int b = 0; b < 8; ++b) {
                float w[16];
                int base = b * 512 + lane;
                #pragma unroll
                for (int j = 0; j < 16; ++j) w[j] = __ldg(wi_row + base + j * 32);
                #pragma unroll
                for (int j = 0; j < 16; ++j) acc += w[j] * g_inp[base + j * 32];
            }
            if (lane == 0) acc += wi_row[4096] * g_inp[4096];
            if (hnz) {
                const float4* wh_row = Wh4 + (size_t)row * DV;
                const float4* curh4  = (const float4*)cur_h;
                #pragma unroll
                for (int b = 0; b < 2; ++b) {
                    float4 w[8];
                    int base = b * 256 + lane;
                    #pragma unroll
                    for (int j = 0; j < 8; ++j) w[j] = __ldg(wh_row + base + j * 32);
                    #pragma unroll
                    for (int j = 0; j < 8; ++j) {
                        float4 h = __ldg(curh4 + base + j * 32);
                        acc += w[j].x * h.x + w[j].y * h.y + w[j].z * h.z + w[j].w * h.w;
                    }
                }
            }
            #pragma unroll
            for (int o = 16; o; o >>= 1) acc += __shfl_down_sync(0xffffffffu, acc, o);
            if (lane == 0) g_gsum[row] = acc + bi[row] + bh[row];
        }
    }
    grid_bar();

    // ---- P6: output matvec partials with fused LSTM gates ----
    for (int vt = blockIdx.x; vt < 512; vt += NBLK) {
        int kc = vt >> 5, nb = vt & 31;
        int k0 = kc * 128;
        __syncthreads();                       // guard vsh reuse across tiles
        if (t < 128) {
            int k = k0 + t;
            float i_g = sigf(g_gsum[k]);
            float f_g = sigf(g_gsum[D + k]);
            float g_g = tanhf(g_gsum[2 * D + k]);
            float o_g = sigf(g_gsum[3 * D + k]);
            float nc  = f_g * cur_cell[k] + i_g * g_g;
            vsh[t] = o_g * tanhf(nc);
        }
        __syncthreads();
        int n4 = nb * 256 + t;
        if (n4 < NTV) {
            float4 a = make_float4(0.f, 0.f, 0.f, 0.f);
            #pragma unroll 1
            for (int kb = 0; kb < 128; kb += 16) {
                float4 w[16];
                #pragma unroll
                for (int j = 0; j < 16; ++j)
                    w[j] = dim_out4[(size_t)(k0 + kb + j) * NTV + n4];
                #pragma unroll
                for (int j = 0; j < 16; ++j) {
                    float h = vsh[kb + j];
                    a.x += h * w[j].x; a.y += h * w[j].y;
                    a.z += h * w[j].z; a.w += h * w[j].w;
                }
            }
            ((float4*)g_pout)[kc * NTV + n4] = a;
        }
    }
    grid_bar();

    // ---- P7: output reduce ----
    for (int n4 = g; n4 < NTV; n4 += NTHR) {
        float4 a = make_float4(0.f, 0.f, 0.f, 0.f);
        #pragma unroll
        for (int k = 0; k < 16; ++k) {
            float4 v = ((const float4*)g_pout)[k * NTV + n4];
            a.x += v.x; a.y += v.y; a.z += v.z; a.w += v.w;
        }
        ((float4*)out)[n4] = a;
    }
}

// ---------------- launcher ----------------
// Inputs: 0 sen_emb [D], 1 hiddens [S,D], 2 pos_index [1], 3 dim_up [D,D],
// 4 dim_down [D,D], 5 dim_out [D,NT], 6 W_gcn [D,D], 7 att_w (unused; softmax
// over identical rows is exactly uniform), 8 Wi [4,D,INP], 9 Wh [4,D,D],
// 10 bi, 11 bh, 12 cur_h [D], 13 cur_cell [D]
extern "C" void kernel_launch(void* const* d_in, const int* in_sizes, int n_in,
                              void* d_out, int out_size) {
    const float* sen_emb  = (const float*)d_in[0];
    const float* hiddens  = (const float*)d_in[1];
    const int*   pos_raw  = (const int*)  d_in[2];
    const float* dim_up   = (const float*)d_in[3];
    const float* dim_down = (const float*)d_in[4];
    const float* dim_out  = (const float*)d_in[5];
    const float* W_gcn    = (const float*)d_in[6];
    const float* Wi       = (const float*)d_in[8];
    const float* Wh       = (const float*)d_in[9];
    const float* bi       = (const float*)d_in[10];
    const float* bh       = (const float*)d_in[11];
    const float* cur_h    = (const float*)d_in[12];
    const float* cur_cell = (const float*)d_in[13];
    float* out = (float*)d_out;

    k_mega<<<NBLK, 256>>>(
        sen_emb, pos_raw,
        (const float4*)hiddens,
        (const float4*)dim_up, (const float4*)W_gcn,
        (const float4*)dim_down, (const float4*)dim_out,
        Wi, (const float4*)Wh, bi, bh,
        cur_h, cur_cell, out);
}

// round 15
// speedup vs baseline: 1.0736x; 1.0736x over previous
#include <cuda_runtime.h>
#include <cstdint>
#include <cstddef>

// Problem constants
#define S_LEN 4096
#define D 2048
#define DV 512            // D / 4 (float4 columns)
#define NT 32000
#define NTV 8000          // NT / 4
#define INP 4097          // D + D + 1
#define N_NODES 4097      // S_LEN + 1
#define NP 256            // partial chunks for colsum / lmv stages
#define NBLK 592          // 4 blocks/SM on 148 SMs (co-resident: 64 regs, 1024 thr/SM)
#define NTHR (NBLK * 256)
#define NWARP (NTHR / 32)

// ---------------- scratch (device globals; no allocation) ----------------
__device__ float g_bufA[NP * D];        // partial ping (2 MB)
__device__ float g_bufB[NP * D];        // partial pong (2 MB)
__device__ float g_inp[INP];            // LSTM input vector
__device__ float g_gsum[4 * D];         // gate pre-activations
__device__ float g_pout[16 * NT];       // output matvec partials (2 MB)
__device__ unsigned g_hbits[D / 32];    // per-warp ballots of cur_h != 0
__device__ unsigned g_hflag;            // OR of g_hbits (rewritten every launch)
__device__ unsigned g_bar_cnt;          // zero-init; always returns to 0
__device__ volatile unsigned g_bar_gen; // monotonically increasing generation

// ---------------- grid-wide barrier (all NBLK blocks co-resident) --------
__device__ __forceinline__ void grid_bar() {
    __syncthreads();
    if (threadIdx.x == 0) {
        unsigned gen = g_bar_gen;
        __threadfence();                       // publish this block's phase writes
        if (atomicAdd(&g_bar_cnt, 1u) == NBLK - 1u) {
            g_bar_cnt = 0u;
            __threadfence();                   // reset visible before release
            g_bar_gen = gen + 1u;
        } else {
            while (g_bar_gen == gen) { }
        }
    }
    __syncthreads();
}

__device__ __forceinline__ float sigf(float x) { return 1.f / (1.f + expf(-x)); }

// Fused matvec stage over 512 tiles (256 k-chunks x 2 column halves).
// W rows prefetched first so their DRAM latency overlaps the prologue reduce.
__device__ void lmv_stage(const float* __restrict__ partin,
                          const float4* __restrict__ W4,
                          float* __restrict__ partout,
                          const float* __restrict__ addvec,
                          float scale, int do_relu,
                          float* red, float* vsh) {
    int t = threadIdx.x;
    for (int vt = blockIdx.x; vt < 512; vt += NBLK) {
        int ky = vt >> 1;
        int k0 = ky * 8;
        int c4 = (vt & 1) * 256 + t;
        // prefetch the 8 W rows this tile streams
        float4 w[8];
        #pragma unroll
        for (int j = 0; j < 8; ++j)
            w[j] = W4[(size_t)(k0 + j) * DV + c4];
        // prologue: reduce partin over NP chunks for columns k0..k0+7
        {
            int c  = k0 + (t & 7);
            int p0 = t >> 3;                   // 0..31
            float acc = 0.f;
            #pragma unroll
            for (int i = 0; i < 8; ++i)
                acc += partin[(p0 + i * 32) * D + c];
            __syncthreads();                   // guard red reuse across tiles
            red[t] = acc;
        }
        __syncthreads();
        #pragma unroll
        for (int s = 128; s >= 8; s >>= 1) {
            if (t < s) red[t] += red[t + s];
            __syncthreads();
        }
        if (t < 8) {
            float v = red[t];
            if (addvec) v += addvec[k0 + t];
            v *= scale;
            if (do_relu) v = fmaxf(v, 0.f);
            vsh[t] = v;
        }
        __syncthreads();
        float4 a = make_float4(0.f, 0.f, 0.f, 0.f);
        #pragma unroll
        for (int j = 0; j < 8; ++j) {
            float s_ = vsh[j];
            a.x += s_ * w[j].x; a.y += s_ * w[j].y;
            a.z += s_ * w[j].z; a.w += s_ * w[j].w;
        }
        ((float4*)partout)[ky * DV + c4] = a;
    }
}

// ---------------- the whole network in one persistent kernel -------------
__global__ void __launch_bounds__(256, 4) k_mega(
        const float* __restrict__ sen, const int* __restrict__ pos_raw,
        const float4* __restrict__ hid4,
        const float4* __restrict__ dim_up4, const float4* __restrict__ W_gcn4,
        const float4* __restrict__ dim_down4, const float4* __restrict__ dim_out4,
        const float* __restrict__ Wi, const float4* __restrict__ Wh4,
        const float* __restrict__ bi, const float* __restrict__ bh,
        const float* __restrict__ cur_h, const float* __restrict__ cur_cell,
        float* __restrict__ out) {
    __shared__ float red[256];
    __shared__ float vsh[128];
    int t = threadIdx.x;
    int g = blockIdx.x * 256 + t;
    int wg = g >> 5, lane = t & 31;

    // ---- P0: prep g_inp, ballot cur_h nonzeros, colsum partials -> bufA ----
    if (g < D) {
        g_inp[g] = sen[g];                     // sen_emb half of LSTM input
        unsigned b = __ballot_sync(0xffffffffu, cur_h[g] != 0.f);
        if (lane == 0) g_hbits[wg] = b;        // always overwritten: deterministic
    }
    if (g == D) {
        int bits = pos_raw[0];
        g_inp[2 * D] = (bits >= 0 && bits < 1000000) ? (float)bits
                                                     : __int_as_float(bits);
    }
    for (int item = g; item < NP * DV; item += NTHR) {
        int chunk = item >> 9, c4 = item & 511;
        float4 a = make_float4(0.f, 0.f, 0.f, 0.f);
        #pragma unroll
        for (int half = 0; half < 2; ++half) {
            float4 w[8];
            #pragma unroll
            for (int r = 0; r < 8; ++r)
                w[r] = hid4[(size_t)(chunk * 16 + half * 8 + r) * DV + c4];
            #pragma unroll
            for (int r = 0; r < 8; ++r) {
                a.x += w[r].x; a.y += w[r].y; a.z += w[r].z; a.w += w[r].w;
            }
        }
        ((float4*)g_bufA)[item] = a;           // item == chunk*DV + c4
    }
    grid_bar();

    // ---- P1..P3: graph chain ----
    lmv_stage(g_bufA, dim_up4,   g_bufB, nullptr, 1.0f, 0, red, vsh);
    grid_bar();
    lmv_stage(g_bufB, W_gcn4,    g_bufA, cur_h, 1.0f / (float)N_NODES, 0, red, vsh);
    grid_bar();
    lmv_stage(g_bufA, dim_down4, g_bufB, nullptr, 1.0f, 1, red, vsh);
    grid_bar();

    // ---- P4: final reduce of dim_down partials -> g_inp[D : 2D); flag OR ----
    if (g == 0) {
        unsigned f = 0;
        #pragma unroll
        for (int i = 0; i < D / 32; ++i) f |= g_hbits[i];
        g_hflag = f;                           // always overwritten: deterministic
    }
    for (int c = wg; c < D; c += NWARP) {
        float a = 0.f;
        #pragma unroll
        for (int i = 0; i < 8; ++i)
            a += g_bufB[(lane + i * 32) * D + c];
        #pragma unroll
        for (int o = 16; o; o >>= 1) a += __shfl_down_sync(0xffffffffu, a, o);
        if (lane == 0) g_inp[D + c] = a;
    }
    grid_bar();

    // ---- P5: LSTM gate pre-activations, warp per (gate,row) ----
    // Wh stream skipped when cur_h is identically zero (runtime-guarded).
    {
        unsigned hnz = g_hflag;
        for (int row = wg; row < 4 * D; row += NWARP) {
            const float* wi_row = Wi + (size_t)row * INP;
            float acc = 0.f;
            #pragma unroll
            for (int b = 0; b < 16; ++b) {
                float w[8];
                int base = b * 256 + lane;
                #pragma unroll
                for (int j = 0; j < 8; ++j) w[j] = __ldg(wi_row + base + j * 32);
                #pragma unroll
                for (int j = 0; j < 8; ++j) acc += w[j] * g_inp[base + j * 32];
            }
            if (lane == 0) acc += wi_row[4096] * g_inp[4096];
            if (hnz) {
                const float4* wh_row = Wh4 + (size_t)row * DV;
                const float4* curh4  = (const float4*)cur_h;
                #pragma unroll
                for (int b = 0; b < 2; ++b) {
                    float4 w[8];
                    int base = b * 256 + lane;
                    #pragma unroll
                    for (int j = 0; j < 8; ++j) w[j] = __ldg(wh_row + base + j * 32);
                    #pragma unroll
                    for (int j = 0; j < 8; ++j) {
                        float4 h = __ldg(curh4 + base + j * 32);
                        acc += w[j].x * h.x + w[j].y * h.y + w[j].z * h.z + w[j].w * h.w;
                    }
                }
            }
            #pragma unroll
            for (int o = 16; o; o >>= 1) acc += __shfl_down_sync(0xffffffffu, acc, o);
            if (lane == 0) g_gsum[row] = acc + bi[row] + bh[row];
        }
    }
    grid_bar();

    // ---- P6: output matvec partials with fused LSTM gates ----
    for (int vt = blockIdx.x; vt < 512; vt += NBLK) {
        int kc = vt >> 5, nb = vt & 31;
        int k0 = kc * 128;
        __syncthreads();                       // guard vsh reuse across tiles
        if (t < 128) {
            int k = k0 + t;
            float i_g = sigf(g_gsum[k]);
            float f_g = sigf(g_gsum[D + k]);
            float g_g = tanhf(g_gsum[2 * D + k]);
            float o_g = sigf(g_gsum[3 * D + k]);
            float nc  = f_g * cur_cell[k] + i_g * g_g;
            vsh[t] = o_g * tanhf(nc);
        }
        __syncthreads();
        int n4 = nb * 256 + t;
        if (n4 < NTV) {
            float4 a = make_float4(0.f, 0.f, 0.f, 0.f);
            #pragma unroll 1
            for (int kb = 0; kb < 128; kb += 8) {
                float4 w[8];
                #pragma unroll
                for (int j = 0; j < 8; ++j)
                    w[j] = dim_out4[(size_t)(k0 + kb + j) * NTV + n4];
                #pragma unroll
                for (int j = 0; j < 8; ++j) {
                    float h = vsh[kb + j];
                    a.x += h * w[j].x; a.y += h * w[j].y;
                    a.z += h * w[j].z; a.w += h * w[j].w;
                }
            }
            ((float4*)g_pout)[kc * NTV + n4] = a;
        }
    }
    grid_bar();

    // ---- P7: output reduce ----
    for (int n4 = g; n4 < NTV; n4 += NTHR) {
        float4 a = make_float4(0.f, 0.f, 0.f, 0.f);
        #pragma unroll
        for (int k = 0; k < 16; ++k) {
            float4 v = ((const float4*)g_pout)[k * NTV + n4];
            a.x += v.x; a.y += v.y; a.z += v.z; a.w += v.w;
        }
        ((float4*)out)[n4] = a;
    }
}

// ---------------- launcher ----------------
// Inputs: 0 sen_emb [D], 1 hiddens [S,D], 2 pos_index [1], 3 dim_up [D,D],
// 4 dim_down [D,D], 5 dim_out [D,NT], 6 W_gcn [D,D], 7 att_w (unused; softmax
// over identical rows is exactly uniform), 8 Wi [4,D,INP], 9 Wh [4,D,D],
// 10 bi, 11 bh, 12 cur_h [D], 13 cur_cell [D]
extern "C" void kernel_launch(void* const* d_in, const int* in_sizes, int n_in,
                              void* d_out, int out_size) {
    const float* sen_emb  = (const float*)d_in[0];
    const float* hiddens  = (const float*)d_in[1];
    const int*   pos_raw  = (const int*)  d_in[2];
    const float* dim_up   = (const float*)d_in[3];
    const float* dim_down = (const float*)d_in[4];
    const float* dim_out  = (const float*)d_in[5];
    const float* W_gcn    = (const float*)d_in[6];
    const float* Wi       = (const float*)d_in[8];
    const float* Wh       = (const float*)d_in[9];
    const float* bi       = (const float*)d_in[10];
    const float* bh       = (const float*)d_in[11];
    const float* cur_h    = (const float*)d_in[12];
    const float* cur_cell = (const float*)d_in[13];
    float* out = (float*)d_out;

    k_mega<<<NBLK, 256>>>(
        sen_emb, pos_raw,
        (const float4*)hiddens,
        (const float4*)dim_up, (const float4*)W_gcn,
        (const float4*)dim_down, (const float4*)dim_out,
        Wi, (const float4*)Wh, bi, bh,
        cur_h, cur_cell, out);
}

// round 16
// speedup vs baseline: 1.1043x; 1.0286x over previous
#include <cuda_runtime.h>
#include <cstdint>
#include <cstddef>

// Problem constants
#define S_LEN 4096
#define D 2048
#define DV 512            // D / 4 (float4 columns)
#define NT 32000
#define NTV 8000          // NT / 4
#define INP 4097          // D + D + 1
#define N_NODES 4097      // S_LEN + 1
#define NP 256            // partial chunks for colsum / lmv stages
#define NBLK 296          // 2 blocks/SM on 148 SMs (co-resident by launch_bounds)
#define NTHR (NBLK * 256)
#define NWARP (NTHR / 32)
#define NSUB 8            // barrier sub-counters (296 = 8 * 37)
#define SUBSZ (NBLK / NSUB)

// ---------------- scratch (device globals; no allocation) ----------------
__device__ float g_bufA[NP * D];        // partial ping (2 MB)
__device__ float g_bufB[NP * D];        // partial pong (2 MB)
__device__ float g_inp[INP];            // LSTM input vector
__device__ float g_gsum[4 * D];         // gate pre-activations
__device__ float g_pout[16 * NT];       // output matvec partials (2 MB)
__device__ unsigned g_hbits[D / 32];    // per-warp ballots of cur_h != 0
__device__ unsigned g_hflag;            // OR of g_hbits (rewritten every launch)
// hierarchical barrier state: sub-counters on separate 128B lines
__device__ unsigned g_bar_sub[NSUB * 32];   // [i*32] used; rest padding
__device__ unsigned g_bar_root;             // zero-init; returns to 0
__device__ volatile unsigned g_bar_gen;     // monotonically increasing

// ---------------- 2-level grid barrier (all NBLK blocks co-resident) -----
__device__ __forceinline__ void grid_bar() {
    __syncthreads();
    if (threadIdx.x == 0) {
        unsigned gen = g_bar_gen;
        __threadfence();                       // publish this block's phase writes
        unsigned sub = blockIdx.x & (NSUB - 1);
        if (atomicAdd(&g_bar_sub[sub * 32], 1u) == SUBSZ - 1u) {
            g_bar_sub[sub * 32] = 0u;          // reset own sub-counter
            if (atomicAdd(&g_bar_root, 1u) == NSUB - 1u) {
                g_bar_root = 0u;
                __threadfence();               // resets visible before release
                g_bar_gen = gen + 1u;
            } else {
                while (g_bar_gen == gen) { }
            }
        } else {
            while (g_bar_gen == gen) { }
        }
    }
    __syncthreads();
}

__device__ __forceinline__ float sigf(float x) { return 1.f / (1.f + expf(-x)); }

// Fused matvec stage over 512 tiles (256 k-chunks x 2 column halves).
// W rows prefetched (evict-first) so DRAM latency overlaps the prologue.
__device__ void lmv_stage(const float* __restrict__ partin,
                          const float4* __restrict__ W4,
                          float* __restrict__ partout,
                          const float* __restrict__ addvec,
                          float scale, int do_relu,
                          float* red, float* vsh) {
    int t = threadIdx.x;
    for (int vt = blockIdx.x; vt < 512; vt += NBLK) {
        int ky = vt >> 1;
        int k0 = ky * 8;
        int c4 = (vt & 1) * 256 + t;
        // prefetch the 8 W rows this tile streams (read-once: evict-first)
        float4 w[8];
        #pragma unroll
        for (int j = 0; j < 8; ++j)
            w[j] = __ldcs(W4 + (size_t)(k0 + j) * DV + c4);
        // prologue: reduce partin over NP chunks for columns k0..k0+7
        {
            int c  = k0 + (t & 7);
            int p0 = t >> 3;                   // 0..31
            float acc = 0.f;
            #pragma unroll
            for (int i = 0; i < 8; ++i)
                acc += partin[(p0 + i * 32) * D + c];
            __syncthreads();                   // guard red reuse across tiles
            red[t] = acc;
        }
        __syncthreads();
        #pragma unroll
        for (int s = 128; s >= 8; s >>= 1) {
            if (t < s) red[t] += red[t + s];
            __syncthreads();
        }
        if (t < 8) {
            float v = red[t];
            if (addvec) v += addvec[k0 + t];
            v *= scale;
            if (do_relu) v = fmaxf(v, 0.f);
            vsh[t] = v;
        }
        __syncthreads();
        float4 a = make_float4(0.f, 0.f, 0.f, 0.f);
        #pragma unroll
        for (int j = 0; j < 8; ++j) {
            float s_ = vsh[j];
            a.x += s_ * w[j].x; a.y += s_ * w[j].y;
            a.z += s_ * w[j].z; a.w += s_ * w[j].w;
        }
        ((float4*)partout)[ky * DV + c4] = a;
    }
}

// ---------------- the whole network in one persistent kernel -------------
__global__ void __launch_bounds__(256, 2) k_mega(
        const float* __restrict__ sen, const int* __restrict__ pos_raw,
        const float4* __restrict__ hid4,
        const float4* __restrict__ dim_up4, const float4* __restrict__ W_gcn4,
        const float4* __restrict__ dim_down4, const float4* __restrict__ dim_out4,
        const float* __restrict__ Wi, const float4* __restrict__ Wh4,
        const float* __restrict__ bi, const float* __restrict__ bh,
        const float* __restrict__ cur_h, const float* __restrict__ cur_cell,
        float* __restrict__ out) {
    __shared__ float red[256];
    __shared__ float vsh[128];
    int t = threadIdx.x;
    int g = blockIdx.x * 256 + t;
    int wg = g >> 5, lane = t & 31;

    // ---- P0: prep g_inp, ballot cur_h nonzeros, colsum partials -> bufA ----
    if (g < D) {
        g_inp[g] = sen[g];                     // sen_emb half of LSTM input
        unsigned b = __ballot_sync(0xffffffffu, cur_h[g] != 0.f);
        if (lane == 0) g_hbits[wg] = b;        // always overwritten: deterministic
    }
    if (g == D) {
        int bits = pos_raw[0];
        g_inp[2 * D] = (bits >= 0 && bits < 1000000) ? (float)bits
                                                     : __int_as_float(bits);
    }
    for (int item = g; item < NP * DV; item += NTHR) {
        int chunk = item >> 9, c4 = item & 511;
        float4 w[16];
        #pragma unroll
        for (int r = 0; r < 16; ++r)
            w[r] = __ldcs(hid4 + (size_t)(chunk * 16 + r) * DV + c4);
        float4 a = make_float4(0.f, 0.f, 0.f, 0.f);
        #pragma unroll
        for (int r = 0; r < 16; ++r) {
            a.x += w[r].x; a.y += w[r].y; a.z += w[r].z; a.w += w[r].w;
        }
        ((float4*)g_bufA)[item] = a;           // item == chunk*DV + c4
    }
    grid_bar();

    // ---- P1..P3: graph chain ----
    lmv_stage(g_bufA, dim_up4,   g_bufB, nullptr, 1.0f, 0, red, vsh);
    grid_bar();
    lmv_stage(g_bufB, W_gcn4,    g_bufA, cur_h, 1.0f / (float)N_NODES, 0, red, vsh);
    grid_bar();
    lmv_stage(g_bufA, dim_down4, g_bufB, nullptr, 1.0f, 1, red, vsh);
    grid_bar();

    // ---- P4: final reduce of dim_down partials -> g_inp[D : 2D); flag OR ----
    if (g == 0) {
        unsigned f = 0;
        #pragma unroll
        for (int i = 0; i < D / 32; ++i) f |= g_hbits[i];
        g_hflag = f;                           // always overwritten: deterministic
    }
    for (int c = wg; c < D; c += NWARP) {
        float a = 0.f;
        #pragma unroll
        for (int i = 0; i < 8; ++i)
            a += g_bufB[(lane + i * 32) * D + c];
        #pragma unroll
        for (int o = 16; o; o >>= 1) a += __shfl_down_sync(0xffffffffu, a, o);
        if (lane == 0) g_inp[D + c] = a;
    }
    grid_bar();

    // ---- P5: LSTM gate pre-activations, warp per (gate,row) ----
    // Wh stream skipped when cur_h is identically zero (runtime-guarded).
    {
        unsigned hnz = g_hflag;
        for (int row = wg; row < 4 * D; row += NWARP) {
            const float* wi_row = Wi + (size_t)row * INP;
            float acc = 0.f;
            #pragma unroll
            for (int b = 0; b < 8; ++b) {
                float w[16];
                int base = b * 512 + lane;
                #pragma unroll
                for (int j = 0; j < 16; ++j) w[j] = __ldcs(wi_row + base + j * 32);
                #pragma unroll
                for (int j = 0; j < 16; ++j) acc += w[j] * g_inp[base + j * 32];
            }
            if (lane == 0) acc += wi_row[4096] * g_inp[4096];
            if (hnz) {
                const float4* wh_row = Wh4 + (size_t)row * DV;
                const float4* curh4  = (const float4*)cur_h;
                #pragma unroll
                for (int b = 0; b < 2; ++b) {
                    float4 w[8];
                    int base = b * 256 + lane;
                    #pragma unroll
                    for (int j = 0; j < 8; ++j) w[j] = __ldcs(wh_row + base + j * 32);
                    #pragma unroll
                    for (int j = 0; j < 8; ++j) {
                        float4 h = __ldg(curh4 + base + j * 32);
                        acc += w[j].x * h.x + w[j].y * h.y + w[j].z * h.z + w[j].w * h.w;
                    }
                }
            }
            #pragma unroll
            for (int o = 16; o; o >>= 1) acc += __shfl_down_sync(0xffffffffu, acc, o);
            if (lane == 0) g_gsum[row] = acc + bi[row] + bh[row];
        }
    }
    grid_bar();

    // ---- P6: output matvec partials with fused LSTM gates ----
    for (int vt = blockIdx.x; vt < 512; vt += NBLK) {
        int kc = vt >> 5, nb = vt & 31;
        int k0 = kc * 128;
        __syncthreads();                       // guard vsh reuse across tiles
        if (t < 128) {
            int k = k0 + t;
            float i_g = sigf(g_gsum[k]);
            float f_g = sigf(g_gsum[D + k]);
            float g_g = tanhf(g_gsum[2 * D + k]);
            float o_g = sigf(g_gsum[3 * D + k]);
            float nc  = f_g * cur_cell[k] + i_g * g_g;
            vsh[t] = o_g * tanhf(nc);
        }
        __syncthreads();
        int n4 = nb * 256 + t;
        if (n4 < NTV) {
            float4 a = make_float4(0.f, 0.f, 0.f, 0.f);
            #pragma unroll 1
            for (int kb = 0; kb < 128; kb += 16) {
                float4 w[16];
                #pragma unroll
                for (int j = 0; j < 16; ++j)
                    w[j] = __ldcs(dim_out4 + (size_t)(k0 + kb + j) * NTV + n4);
                #pragma unroll
                for (int j = 0; j < 16; ++j) {
                    float h = vsh[kb + j];
                    a.x += h * w[j].x; a.y += h * w[j].y;
                    a.z += h * w[j].z; a.w += h * w[j].w;
                }
            }
            ((float4*)g_pout)[kc * NTV + n4] = a;
        }
    }
    grid_bar();

    // ---- P7: output reduce ----
    for (int n4 = g; n4 < NTV; n4 += NTHR) {
        float4 a = make_float4(0.f, 0.f, 0.f, 0.f);
        #pragma unroll
        for (int k = 0; k < 16; ++k) {
            float4 v = ((const float4*)g_pout)[k * NTV + n4];
            a.x += v.x; a.y += v.y; a.z += v.z; a.w += v.w;
        }
        ((float4*)out)[n4] = a;
    }
}

// ---------------- launcher ----------------
// Inputs: 0 sen_emb [D], 1 hiddens [S,D], 2 pos_index [1], 3 dim_up [D,D],
// 4 dim_down [D,D], 5 dim_out [D,NT], 6 W_gcn [D,D], 7 att_w (unused; softmax
// over identical rows is exactly uniform), 8 Wi [4,D,INP], 9 Wh [4,D,D],
// 10 bi, 11 bh, 12 cur_h [D], 13 cur_cell [D]
extern "C" void kernel_launch(void* const* d_in, const int* in_sizes, int n_in,
                              void* d_out, int out_size) {
    const float* sen_emb  = (const float*)d_in[0];
    const float* hiddens  = (const float*)d_in[1];
    const int*   pos_raw  = (const int*)  d_in[2];
    const float* dim_up   = (const float*)d_in[3];
    const float* dim_down = (const float*)d_in[4];
    const float* dim_out  = (const float*)d_in[5];
    const float* W_gcn    = (const float*)d_in[6];
    const float* Wi       = (const float*)d_in[8];
    const float* Wh       = (const float*)d_in[9];
    const float* bi       = (const float*)d_in[10];
    const float* bh       = (const float*)d_in[11];
    const float* cur_h    = (const float*)d_in[12];
    const float* cur_cell = (const float*)d_in[13];
    float* out = (float*)d_out;

    k_mega<<<NBLK, 256>>>(
        sen_emb, pos_raw,
        (const float4*)hiddens,
        (const float4*)dim_up, (const float4*)W_gcn,
        (const float4*)dim_down, (const float4*)dim_out,
        Wi, (const float4*)Wh, bi, bh,
        cur_h, cur_cell, out);
}

// round 17
// speedup vs baseline: 1.1414x; 1.0335x over previous
#include <cuda_runtime.h>
#include <cstdint>
#include <cstddef>

// Problem constants
#define S_LEN 4096
#define D 2048
#define DV 512            // D / 4 (float4 columns)
#define NT 32000
#define NTV 8000          // NT / 4
#define INP 4097          // D + D + 1
#define N_NODES 4097      // S_LEN + 1
#define NP 256            // partial chunks for colsum / lmv stages
#define NBLK 296          // 2 blocks/SM on 148 SMs (co-resident by launch_bounds)
#define NTHR (NBLK * 256)
#define NWARP (NTHR / 32)
#define NSUB 8            // barrier sub-counters (296 = 8 * 37)
#define SUBSZ (NBLK / NSUB)

// ---------------- scratch (device globals; no allocation) ----------------
__device__ float g_bufA[NP * D];        // partial ping (2 MB)
__device__ float g_bufB[NP * D];        // partial pong (2 MB)
__device__ float g_inp[INP];            // LSTM input vector
__device__ float g_gsum[4 * D];         // gate pre-activations
__device__ float g_pout[16 * NT];       // output matvec partials (2 MB)
__device__ unsigned g_hbits[D / 32];    // per-warp ballots of cur_h != 0
__device__ unsigned g_hflag;            // OR of g_hbits (rewritten every launch)
__device__ unsigned g_cnt5[16];         // per-k-chunk gate completion (->512)
__device__ unsigned g_cnt6[32];         // per-nb output-partial completion (->16)
__device__ unsigned g_tk6;              // P6 ticket counter
// hierarchical barrier state: sub-counters on separate 128B lines
__device__ unsigned g_bar_sub[NSUB * 32];   // [i*32] used; rest padding
__device__ unsigned g_bar_root;             // zero-init; returns to 0
__device__ volatile unsigned g_bar_gen;     // monotonically increasing

// ---------------- 2-level grid barrier (all NBLK blocks co-resident) -----
__device__ __forceinline__ void grid_bar() {
    __syncthreads();
    if (threadIdx.x == 0) {
        unsigned gen = g_bar_gen;
        __threadfence();                       // publish this block's phase writes
        unsigned sub = blockIdx.x & (NSUB - 1);
        if (atomicAdd(&g_bar_sub[sub * 32], 1u) == SUBSZ - 1u) {
            g_bar_sub[sub * 32] = 0u;          // reset own sub-counter
            if (atomicAdd(&g_bar_root, 1u) == NSUB - 1u) {
                g_bar_root = 0u;
                __threadfence();               // resets visible before release
                g_bar_gen = gen + 1u;
            } else {
                while (g_bar_gen == gen) { }
            }
        } else {
            while (g_bar_gen == gen) { }
        }
    }
    __syncthreads();
}

__device__ __forceinline__ float sigf(float x) { return 1.f / (1.f + expf(-x)); }

// Fused matvec stage over 512 tiles (256 k-chunks x 2 column halves).
// W rows prefetched (evict-first) so DRAM latency overlaps the prologue.
__device__ void lmv_stage(const float* __restrict__ partin,
                          const float4* __restrict__ W4,
                          float* __restrict__ partout,
                          const float* __restrict__ addvec,
                          float scale, int do_relu,
                          float* red, float* vsh) {
    int t = threadIdx.x;
    for (int vt = blockIdx.x; vt < 512; vt += NBLK) {
        int ky = vt >> 1;
        int k0 = ky * 8;
        int c4 = (vt & 1) * 256 + t;
        float4 w[8];
        #pragma unroll
        for (int j = 0; j < 8; ++j)
            w[j] = __ldcs(W4 + (size_t)(k0 + j) * DV + c4);
        {
            int c  = k0 + (t & 7);
            int p0 = t >> 3;                   // 0..31
            float acc = 0.f;
            #pragma unroll
            for (int i = 0; i < 8; ++i)
                acc += partin[(p0 + i * 32) * D + c];
            __syncthreads();                   // guard red reuse across tiles
            red[t] = acc;
        }
        __syncthreads();
        #pragma unroll
        for (int s = 128; s >= 8; s >>= 1) {
            if (t < s) red[t] += red[t + s];
            __syncthreads();
        }
        if (t < 8) {
            float v = red[t];
            if (addvec) v += addvec[k0 + t];
            v *= scale;
            if (do_relu) v = fmaxf(v, 0.f);
            vsh[t] = v;
        }
        __syncthreads();
        float4 a = make_float4(0.f, 0.f, 0.f, 0.f);
        #pragma unroll
        for (int j = 0; j < 8; ++j) {
            float s_ = vsh[j];
            a.x += s_ * w[j].x; a.y += s_ * w[j].y;
            a.z += s_ * w[j].z; a.w += s_ * w[j].w;
        }
        ((float4*)partout)[ky * DV + c4] = a;
    }
}

// ---------------- the whole network in one persistent kernel -------------
__global__ void __launch_bounds__(256, 2) k_mega(
        const float* __restrict__ sen, const int* __restrict__ pos_raw,
        const float4* __restrict__ hid4,
        const float4* __restrict__ dim_up4, const float4* __restrict__ W_gcn4,
        const float4* __restrict__ dim_down4, const float4* __restrict__ dim_out4,
        const float* __restrict__ Wi, const float4* __restrict__ Wh4,
        const float* __restrict__ bi, const float* __restrict__ bh,
        const float* __restrict__ cur_h, const float* __restrict__ cur_cell,
        float* __restrict__ out) {
    __shared__ float red[256];
    __shared__ float vsh[128];
    __shared__ unsigned tk_sh;
    int t = threadIdx.x;
    int g = blockIdx.x * 256 + t;
    int wg = g >> 5, lane = t & 31;

    // ---- P0: reset flow counters, prep g_inp, ballots, colsum -> bufA ----
    if (g == 0) {
        #pragma unroll
        for (int i = 0; i < 16; ++i) g_cnt5[i] = 0u;
        #pragma unroll
        for (int i = 0; i < 32; ++i) g_cnt6[i] = 0u;
        g_tk6 = 0u;
    }
    if (g < D) {
        g_inp[g] = sen[g];                     // sen_emb half of LSTM input
        unsigned b = __ballot_sync(0xffffffffu, cur_h[g] != 0.f);
        if (lane == 0) g_hbits[wg] = b;        // always overwritten: deterministic
    }
    if (g == D) {
        int bits = pos_raw[0];
        g_inp[2 * D] = (bits >= 0 && bits < 1000000) ? (float)bits
                                                     : __int_as_float(bits);
    }
    for (int item = g; item < NP * DV; item += NTHR) {
        int chunk = item >> 9, c4 = item & 511;
        float4 w[16];
        #pragma unroll
        for (int r = 0; r < 16; ++r)
            w[r] = __ldcs(hid4 + (size_t)(chunk * 16 + r) * DV + c4);
        float4 a = make_float4(0.f, 0.f, 0.f, 0.f);
        #pragma unroll
        for (int r = 0; r < 16; ++r) {
            a.x += w[r].x; a.y += w[r].y; a.z += w[r].z; a.w += w[r].w;
        }
        ((float4*)g_bufA)[item] = a;           // item == chunk*DV + c4
    }
    grid_bar();

    // ---- P1..P3: graph chain ----
    lmv_stage(g_bufA, dim_up4,   g_bufB, nullptr, 1.0f, 0, red, vsh);
    grid_bar();
    lmv_stage(g_bufB, W_gcn4,    g_bufA, cur_h, 1.0f / (float)N_NODES, 0, red, vsh);
    grid_bar();
    lmv_stage(g_bufA, dim_down4, g_bufB, nullptr, 1.0f, 1, red, vsh);
    grid_bar();

    // ---- P4: final reduce of dim_down partials -> g_inp[D : 2D); flag OR ----
    if (g == 0) {
        unsigned f = 0;
        #pragma unroll
        for (int i = 0; i < D / 32; ++i) f |= g_hbits[i];
        g_hflag = f;                           // always overwritten: deterministic
    }
    for (int c = wg; c < D; c += NWARP) {
        float a = 0.f;
        #pragma unroll
        for (int i = 0; i < 8; ++i)
            a += g_bufB[(lane + i * 32) * D + c];
        #pragma unroll
        for (int o = 16; o; o >>= 1) a += __shfl_down_sync(0xffffffffu, a, o);
        if (lane == 0) g_inp[D + c] = a;
    }
    grid_bar();                                // last full-grid barrier

    // ---- P5: gate pre-activations, chunk-major items + completion flags ----
    // item -> (kc, gate, k): chunk kc completes early-first so P6 can start.
    // Wh stream skipped when cur_h is identically zero (runtime-guarded).
    {
        unsigned hnz = g_hflag;
        for (int it = wg; it < 4 * D; it += NWARP) {
            int kc    = it >> 9;               // 16 chunks x 512 rows
            int inner = it & 511;
            int gate  = inner >> 7;
            int row   = gate * D + kc * 128 + (inner & 127);
            const float* wi_row = Wi + (size_t)row * INP;
            float acc = 0.f;
            #pragma unroll
            for (int b = 0; b < 8; ++b) {
                float w[16];
                int base = b * 512 + lane;
                #pragma unroll
                for (int j = 0; j < 16; ++j) w[j] = __ldcs(wi_row + base + j * 32);
                #pragma unroll
                for (int j = 0; j < 16; ++j) acc += w[j] * g_inp[base + j * 32];
            }
            if (lane == 0) acc += wi_row[4096] * g_inp[4096];
            if (hnz) {
                const float4* wh_row = Wh4 + (size_t)row * DV;
                const float4* curh4  = (const float4*)cur_h;
                #pragma unroll
                for (int b = 0; b < 2; ++b) {
                    float4 w[8];
                    int base = b * 256 + lane;
                    #pragma unroll
                    for (int j = 0; j < 8; ++j) w[j] = __ldcs(wh_row + base + j * 32);
                    #pragma unroll
                    for (int j = 0; j < 8; ++j) {
                        float4 h = __ldg(curh4 + base + j * 32);
                        acc += w[j].x * h.x + w[j].y * h.y + w[j].z * h.z + w[j].w * h.w;
                    }
                }
            }
            #pragma unroll
            for (int o = 16; o; o >>= 1) acc += __shfl_down_sync(0xffffffffu, acc, o);
            if (lane == 0) {
                g_gsum[row] = acc + bi[row] + bh[row];
                __threadfence();               // release the row
                atomicAdd(&g_cnt5[kc], 1u);
            }
        }
    }
    // NO grid barrier: flow straight into P6.

    // ---- P6: output matvec partials, ticket-scheduled, chunk-gated ----
    for (;;) {
        __syncthreads();                       // tk_sh / vsh reuse guard
        if (t == 0) tk_sh = atomicAdd(&g_tk6, 1u);
        __syncthreads();
        unsigned vt = tk_sh;
        if (vt >= 512u) break;
        int kc = (int)(vt >> 5), nb = (int)(vt & 31u);
        int k0 = kc * 128;
        if (t == 0) {                          // wait for this chunk's gates
            while (((volatile unsigned*)g_cnt5)[kc] != 512u) { }
            __threadfence();                   // acquire
        }
        __syncthreads();
        if (t < 128) {
            int k = k0 + t;
            float i_g = sigf(g_gsum[k]);
            float f_g = sigf(g_gsum[D + k]);
            float g_g = tanhf(g_gsum[2 * D + k]);
            float o_g = sigf(g_gsum[3 * D + k]);
            float nc  = f_g * cur_cell[k] + i_g * g_g;
            vsh[t] = o_g * tanhf(nc);
        }
        __syncthreads();
        int n4 = nb * 256 + t;
        if (n4 < NTV) {
            float4 a = make_float4(0.f, 0.f, 0.f, 0.f);
            #pragma unroll 1
            for (int kb = 0; kb < 128; kb += 16) {
                float4 w[16];
                #pragma unroll
                for (int j = 0; j < 16; ++j)
                    w[j] = __ldcs(dim_out4 + (size_t)(k0 + kb + j) * NTV + n4);
                #pragma unroll
                for (int j = 0; j < 16; ++j) {
                    float h = vsh[kb + j];
                    a.x += h * w[j].x; a.y += h * w[j].y;
                    a.z += h * w[j].z; a.w += h * w[j].w;
                }
            }
            ((float4*)g_pout)[kc * NTV + n4] = a;
        }
        __syncthreads();                       // all tile stores done
        if (t == 0) {
            __threadfence();                   // release the tile
            atomicAdd(&g_cnt6[nb], 1u);
        }
    }
    // NO grid barrier: flow straight into P7.

    // ---- P7: output reduce, gated per nb column group ----
    for (int n4 = g; n4 < NTV; n4 += NTHR) {
        int nb = n4 >> 8;
        if (lane == 0) {
            while (((volatile unsigned*)g_cnt6)[nb] != 16u) { }
            __threadfence();                   // acquire
        }
        __syncwarp();
        float4 a = make_float4(0.f, 0.f, 0.f, 0.f);
        #pragma unroll
        for (int k = 0; k < 16; ++k) {
            float4 v = ((const float4*)g_pout)[k * NTV + n4];
            a.x += v.x; a.y += v.y; a.z += v.z; a.w += v.w;
        }
        ((float4*)out)[n4] = a;
    }
}

// ---------------- launcher ----------------
// Inputs: 0 sen_emb [D], 1 hiddens [S,D], 2 pos_index [1], 3 dim_up [D,D],
// 4 dim_down [D,D], 5 dim_out [D,NT], 6 W_gcn [D,D], 7 att_w (unused; softmax
// over identical rows is exactly uniform), 8 Wi [4,D,INP], 9 Wh [4,D,D],
// 10 bi, 11 bh, 12 cur_h [D], 13 cur_cell [D]
extern "C" void kernel_launch(void* const* d_in, const int* in_sizes, int n_in,
                              void* d_out, int out_size) {
    const float* sen_emb  = (const float*)d_in[0];
    const float* hiddens  = (const float*)d_in[1];
    const int*   pos_raw  = (const int*)  d_in[2];
    const float* dim_up   = (const float*)d_in[3];
    const float* dim_down = (const float*)d_in[4];
    const float* dim_out  = (const float*)d_in[5];
    const float* W_gcn    = (const float*)d_in[6];
    const float* Wi       = (const float*)d_in[8];
    const float* Wh       = (const float*)d_in[9];
    const float* bi       = (const float*)d_in[10];
    const float* bh       = (const float*)d_in[11];
    const float* cur_h    = (const float*)d_in[12];
    const float* cur_cell = (const float*)d_in[13];
    float* out = (float*)d_out;

    k_mega<<<NBLK, 256>>>(
        sen_emb, pos_raw,
        (const float4*)hiddens,
        (const float4*)dim_up, (const float4*)W_gcn,
        (const float4*)dim_down, (const float4*)dim_out,
        Wi, (const float4*)Wh, bi, bh,
        cur_h, cur_cell, out);
}